// round 17
// baseline (speedup 1.0000x reference)
#include <cuda_runtime.h>
#include <cuda_bf16.h>
#include <cstdint>

// out[e*12 + 0..11] = W[h][rel_pos[e]]  -> gather of W^T rows.
// R10: R9 (one thread per element, 1 LDG -> 3 LDS -> 3 conflict-free stride-3
// STS, 24KB tiles, 2 buffers) + index LDG hoisted ABOVE the buffer-reuse wait
// (overlaps ~600cyc index latency with the TMA drain) + 16 tiles/CTA.

#define THREADS       512
#define TILE_ELEM     (THREADS)            // 512 elements per tile
#define TILE_F4       (TILE_ELEM * 3)      // 1536 float4 = 24 KB
#define TILES_PER_CTA 16                   // 8192 elements / CTA

__device__ __forceinline__ unsigned smem_u32(const void* p) {
    unsigned a;
    asm("{ .reg .u64 x; cvta.to.shared.u64 x, %1; cvt.u32.u64 %0, x; }"
        : "=r"(a) : "l"(p));
    return a;
}

__global__ __launch_bounds__(THREADS)
void gather_wt_r10(const int* __restrict__ rel_pos,
                   const float* __restrict__ W,       // [12,64]
                   float4* __restrict__ out4)
{
    __shared__ __align__(16)  float4 table4[64 * 3];        // table4[cls*3+c]
    __shared__ __align__(128) float4 stage4[2][TILE_F4];    // 2 x 24 KB

    float* table = reinterpret_cast<float*>(table4);
    unsigned t = threadIdx.x;

    // Transposed table: table[c*12 + h] = W[h*64 + c]
    #pragma unroll
    for (int i = 0; i < 2; i++) {
        unsigned j = t + i * (unsigned)THREADS;   // [0,1024)
        if (j < 768u)
            table[(j & 63u) * 12u + (j >> 6)] = W[j];
    }
    __syncthreads();

    unsigned elem0 = blockIdx.x * (unsigned)(TILE_ELEM * TILES_PER_CTA);

    // Prefetch tile 0's index before anything else.
    int cls = rel_pos[elem0 + t];

    #pragma unroll
    for (int it = 0; it < TILES_PER_CTA; it++) {
        int buf = it & 1;
        unsigned ebase = elem0 + (unsigned)it * (unsigned)TILE_ELEM;

        // Reuse gate AFTER the index prefetch: LDG latency overlaps the drain.
        if (it >= 2) {
            if (t == 0)
                asm volatile("cp.async.bulk.wait_group 1;" ::: "memory");
            __syncthreads();
        }

        // Gather using the prefetched index: 3 row-contiguous LDS.128,
        // 3 conflict-free stride-3 STS.128.
        {
            unsigned r = (unsigned)cls * 3u;
            float4 v0 = table4[r + 0];
            float4 v1 = table4[r + 1];
            float4 v2 = table4[r + 2];
            unsigned s = t * 3u;
            stage4[buf][s + 0] = v0;
            stage4[buf][s + 1] = v1;
            stage4[buf][s + 2] = v2;
        }

        // Prefetch next tile's index before the sync (independent of smem).
        if (it + 1 < TILES_PER_CTA)
            cls = rel_pos[ebase + (unsigned)TILE_ELEM + t];

        __syncthreads();

        // Async bulk store: 24 KB smem -> gmem.
        if (t == 0) {
            unsigned saddr = smem_u32(stage4[buf]);
            unsigned long long gaddr =
                (unsigned long long)(out4 + (size_t)ebase * 3u);
            asm volatile("fence.proxy.async;" ::: "memory");
            asm volatile("cp.async.bulk.global.shared::cta.bulk_group [%0], [%1], %2;"
                         :: "l"(gaddr), "r"(saddr), "n"(TILE_F4 * 16) : "memory");
            asm volatile("cp.async.bulk.commit_group;" ::: "memory");
        }
        // Buffer untouched until its wait above; no extra sync needed.
    }

    // Drain before CTA exit (smem handed to next CTA).
    if (t == 0)
        asm volatile("cp.async.bulk.wait_group 0;" ::: "memory");
    __syncthreads();
}

// Generic tail (unused for the benchmark shapes): direct gather + store.
__global__ __launch_bounds__(256)
void gather_wt_tail(const int* __restrict__ rel_pos,
                    const float* __restrict__ W,
                    float4* __restrict__ out4,
                    unsigned start_elem, unsigned n_elem)
{
    __shared__ float4 table4[64 * 3];
    float* table = reinterpret_cast<float*>(table4);
    unsigned t = threadIdx.x;
    #pragma unroll
    for (int i = 0; i < 3; i++) {
        unsigned j = t + i * 256u;
        table[(j & 63u) * 12u + (j >> 6)] = W[j];
    }
    __syncthreads();

    unsigned e = start_elem + blockIdx.x * 256u + t;
    if (e < n_elem) {
        int cls = rel_pos[e];
        unsigned r = (unsigned)cls * 3u;
        size_t o = (size_t)e * 3u;
        out4[o + 0] = table4[r + 0];
        out4[o + 1] = table4[r + 1];
        out4[o + 2] = table4[r + 2];
    }
}

extern "C" void kernel_launch(void* const* d_in, const int* in_sizes, int n_in,
                              void* d_out, int out_size)
{
    const int*   rel_pos = (const int*)d_in[0];    // [4,2048,2048] int32
    // d_in[1] = hidden_states (unused; dtype carrier only)
    const float* W       = (const float*)d_in[2];  // [12,64] float32
    float4*      out4    = (float4*)d_out;

    unsigned n_elem  = (unsigned)in_sizes[0];      // 16,777,216
    unsigned per_cta = (unsigned)(TILE_ELEM * TILES_PER_CTA);  // 8192 elements
    unsigned blocks  = n_elem / per_cta;           // 2048 exact for bench
    unsigned done    = blocks * per_cta;

    if (blocks)
        gather_wt_r10<<<blocks, THREADS>>>(rel_pos, W, out4);

    if (done < n_elem) {
        unsigned rem = n_elem - done;
        unsigned tb  = (rem + 255u) / 256u;
        gather_wt_tail<<<tb, 256>>>(rel_pos, W, out4, done, n_elem);
    }
}